// round 1
// baseline (speedup 1.0000x reference)
#include <cuda_runtime.h>
#include <cuda_bf16.h>

// SpatialConv (SCNN-style 4-direction recurrent conv) for GB300 sm_103a.
// Shapes: x [B=64, C=128, H=36, W=100], w [128,128,9], b [128].
// 4 sequential passes; each step: s_dst += relu(conv1d(s_src, w) + b).
//
// Strategy (R1): fp32 with packed f32x2 FFMA2 (2x fp32 pipe), SMEM-staged
// input slices + weights, one launch per recurrence step, transpose between
// H-direction and W-direction passes for contiguous conv axis.

#define BB 64
#define CC 128
#define HH 36
#define WW 100
#define KK 9

typedef unsigned long long u64;

__device__ __forceinline__ u64 pack2(float a, float b) {
    u64 r;
    asm("mov.b64 %0, {%1, %2};" : "=l"(r) : "f"(a), "f"(b));
    return r;
}
__device__ __forceinline__ void unpack2(u64 v, float& a, float& b) {
    asm("mov.b64 {%0, %1}, %2;" : "=f"(a), "=f"(b) : "l"(v));
}
__device__ __forceinline__ void ffma2(u64& d, u64 a, u64 b) {
    asm("fma.rn.f32x2 %0, %1, %2, %0;" : "+l"(d) : "l"(a), "l"(b));
}

// Scratch buffer for the transposed tensor [B, C, W, H]
__device__ float g_T[(size_t)BB * CC * WW * HH];

// Generic recurrence step on buffer laid out [B, C, S, L].
//   buf[b, co, s_dst, l] += relu( bias[co] + sum_{ci,k} w[co,ci,k]*buf[b,ci,s_src,l+k-4] )
// Thread layout: blockDim = CP*LG. Each thread: 4 output channels (co = co_base+4*cp+{0..3})
// and NL consecutive l positions (l = l_base + lg*NL + j). Accumulators are f32x2 pairs.
template <int L, int S, int CP, int LG, int NL, int LSPLIT, int CIC>
__global__ __launch_bounds__(CP * LG, 4) void step_kernel(
    float* __restrict__ buf, int s_src, int s_dst,
    const float* __restrict__ w, const float* __restrict__ bias)
{
    constexpr int CO_TILE = 4 * CP;
    constexpr int LW = L / LSPLIT;           // l-range handled by this block
    constexpr int WIN = LG * NL + 8;         // smem input window incl. halo
    constexpr int NT = CP * LG;

    __shared__ __align__(16) float in_s[CC][WIN];
    __shared__ __align__(16) float w_s[CIC][KK][CO_TILE];

    const int tid = threadIdx.x;
    const int cp = tid % CP;
    const int lg = tid / CP;
    const int b = blockIdx.z;
    const int co_base = blockIdx.y * CO_TILE;
    const int l_base = blockIdx.x * LW;

    // Stage input slice [C, window] with zero halo (conv pad = 4).
    for (int idx = tid; idx < CC * WIN; idx += NT) {
        int ci = idx / WIN;
        int j = idx % WIN;
        int gl = l_base + j - 4;
        float v = 0.f;
        if (gl >= 0 && gl < L)
            v = buf[((size_t)(b * CC + ci) * S + s_src) * L + gl];
        in_s[ci][j] = v;
    }

    // Init accumulators with bias (added once, inside the relu).
    u64 acc0[NL], acc1[NL];
    {
        float b0 = bias[co_base + 4 * cp + 0];
        float b1 = bias[co_base + 4 * cp + 1];
        float b2 = bias[co_base + 4 * cp + 2];
        float b3 = bias[co_base + 4 * cp + 3];
#pragma unroll
        for (int j = 0; j < NL; j++) {
            acc0[j] = pack2(b0, b1);
            acc1[j] = pack2(b2, b3);
        }
    }
    __syncthreads();

    for (int cc = 0; cc < CC / CIC; cc++) {
        // Stage weight chunk as [ci][k][co] so 4 co's are one float4.
        for (int idx = tid; idx < CIC * KK * CO_TILE; idx += NT) {
            int co = idx % CO_TILE;
            int k = (idx / CO_TILE) % KK;
            int ci = idx / (CO_TILE * KK);
            w_s[ci][k][co] =
                w[(size_t)(co_base + co) * CC * KK + (cc * CIC + ci) * KK + k];
        }
        __syncthreads();

#pragma unroll 2
        for (int ci = 0; ci < CIC; ci++) {
            const int cig = cc * CIC + ci;
            // Input window for this thread's NL outputs: NL+8 values.
            u64 xx[NL + 8];
#pragma unroll
            for (int t = 0; t < NL + 8; t++) {
                float xv = in_s[cig][lg * NL + t];
                xx[t] = pack2(xv, xv);
            }
#pragma unroll
            for (int k = 0; k < KK; k++) {
                float4 wq = *reinterpret_cast<const float4*>(&w_s[ci][k][4 * cp]);
                u64 w01 = pack2(wq.x, wq.y);
                u64 w23 = pack2(wq.z, wq.w);
#pragma unroll
                for (int j = 0; j < NL; j++) {
                    ffma2(acc0[j], w01, xx[j + k]);
                    ffma2(acc1[j], w23, xx[j + k]);
                }
            }
        }
        __syncthreads();
    }

    // Stage relu(acc) into smem (reuse in_s) so the global += is coalesced.
    float* out_s = &in_s[0][0];  // CO_TILE*LW <= CC*WIN always
#pragma unroll
    for (int j = 0; j < NL; j++) {
        int l = lg * NL + j;
        if (l < LW) {
            float a, bv, c, d;
            unpack2(acc0[j], a, bv);
            unpack2(acc1[j], c, d);
            out_s[(4 * cp + 0) * LW + l] = fmaxf(a, 0.f);
            out_s[(4 * cp + 1) * LW + l] = fmaxf(bv, 0.f);
            out_s[(4 * cp + 2) * LW + l] = fmaxf(c, 0.f);
            out_s[(4 * cp + 3) * LW + l] = fmaxf(d, 0.f);
        }
    }
    __syncthreads();

    for (int idx = tid; idx < CO_TILE * LW; idx += NT) {
        int co = idx / LW;
        int l = idx % LW;
        size_t gi = ((size_t)(b * CC + co_base + co) * S + s_dst) * L + l_base + l;
        buf[gi] += out_s[idx];
    }
}

// Transpose inner two dims: in [BC][R][Cc] -> out [BC][Cc][R]
__global__ void transpose_kernel(const float* __restrict__ in, float* __restrict__ out,
                                 int R, int Cc)
{
    __shared__ float tile[32][33];
    const int bc = blockIdx.z;
    const int c0 = blockIdx.x * 32;
    const int r0 = blockIdx.y * 32;
    const float* ip = in + (size_t)bc * R * Cc;
    float* op = out + (size_t)bc * R * Cc;
    const int tx = threadIdx.x, ty = threadIdx.y;

    for (int i = ty; i < 32; i += 8) {
        int r = r0 + i, c = c0 + tx;
        if (r < R && c < Cc) tile[i][tx] = ip[(size_t)r * Cc + c];
    }
    __syncthreads();
    for (int i = ty; i < 32; i += 8) {
        int c = c0 + i, r = r0 + tx;
        if (c < Cc && r < R) op[(size_t)c * R + r] = tile[tx][i];
    }
}

extern "C" void kernel_launch(void* const* d_in, const int* in_sizes, int n_in,
                              void* d_out, int out_size)
{
    const float* x = (const float*)d_in[0];
    const float* w_d = (const float*)d_in[1];
    const float* b_d = (const float*)d_in[2];
    const float* w_u = (const float*)d_in[3];
    const float* b_u = (const float*)d_in[4];
    const float* w_r = (const float*)d_in[5];
    const float* b_r = (const float*)d_in[6];
    const float* w_l = (const float*)d_in[7];
    const float* b_l = (const float*)d_in[8];
    float* out = (float*)d_out;

    float* T = nullptr;
    cudaGetSymbolAddress((void**)&T, g_T);

    const size_t nbytes = (size_t)BB * CC * HH * WW * sizeof(float);
    cudaMemcpyAsync(out, x, nbytes, cudaMemcpyDeviceToDevice, 0);

    // ---- Down / Up passes: recurrence over H, conv along W (L=100, S=36) ----
    // CP=16 (64 co/block), LG=8, NL=7 (covers LW=50), LSPLIT=2, CIC=4
    dim3 gw(2, CC / 64, BB);
    for (int h = 1; h <= HH - 1; h++)
        step_kernel<WW, HH, 16, 8, 7, 2, 4><<<gw, 128>>>(out, h - 1, h, w_d, b_d);
    for (int h = HH - 2; h >= 1; h--)
        step_kernel<WW, HH, 16, 8, 7, 2, 4><<<gw, 128>>>(out, h + 1, h, w_u, b_u);

    // ---- Transpose [B,C,H,W] -> [B,C,W,H] so H is contiguous ----
    {
        dim3 tb(32, 8);
        dim3 tg((WW + 31) / 32, (HH + 31) / 32, BB * CC);
        transpose_kernel<<<tg, tb>>>(out, T, HH, WW);
    }

    // ---- Right / Left passes: recurrence over W, conv along H (L=36, S=100) ----
    // CP=8 (32 co/block), LG=16, NL=3 (covers 36), LSPLIT=1, CIC=8
    dim3 gh(1, CC / 32, BB);
    for (int wi = 1; wi <= WW - 1; wi++)
        step_kernel<HH, WW, 8, 16, 3, 1, 8><<<gh, 128>>>(T, wi - 1, wi, w_r, b_r);
    for (int wi = WW - 2; wi >= 1; wi--)
        step_kernel<HH, WW, 8, 16, 3, 1, 8><<<gh, 128>>>(T, wi + 1, wi, w_l, b_l);

    // ---- Transpose back [B,C,W,H] -> [B,C,H,W] into d_out ----
    {
        dim3 tb(32, 8);
        dim3 tg((HH + 31) / 32, (WW + 31) / 32, BB * CC);
        transpose_kernel<<<tg, tb>>>(T, out, WW, HH);
    }
}